// round 17
// baseline (speedup 1.0000x reference)
#include <cuda_runtime.h>
#include <cuda_fp16.h>
#include <cstdint>

// Problem constants
#define EMBED   1024
#define NHEAD   16
#define HDIM    64
#define BATCH   4
#define SEQ     2048
#define MROWS   (BATCH * SEQ)                 // 8192
#define QKVN    (BATCH * NHEAD * SEQ * HDIM)  // 8388608

// ---------------------------------------------------------------------------
// Persistent scratch (all single fp16)
// ---------------------------------------------------------------------------
__device__ __align__(16) __half g_x  [MROWS * EMBED];
__device__ __align__(16) __half g_wq [3 * EMBED * EMBED];
__device__ __align__(16) __half g_wp [EMBED * EMBED];
__device__ __align__(16) __half g_q  [QKVN];   // [B,H,T,D], pre-scaled by 0.125
__device__ __align__(16) __half g_k  [QKVN];   // [B,H,T,D]
__device__ __align__(16) __half g_v  [QKVN];   // [B,H,T,D]  (row-major like K)
__device__ __align__(16) __half g_ao [MROWS * EMBED];   // [B*T, C]

// ---------------------------------------------------------------------------
// helpers
// ---------------------------------------------------------------------------
__device__ __forceinline__ void mma_f16(float* c, const uint32_t* a, const uint32_t* b) {
    asm volatile(
        "mma.sync.aligned.m16n8k16.row.col.f32.f16.f16.f32 "
        "{%0,%1,%2,%3}, {%4,%5,%6,%7}, {%8,%9}, {%0,%1,%2,%3};"
        : "+f"(c[0]), "+f"(c[1]), "+f"(c[2]), "+f"(c[3])
        : "r"(a[0]), "r"(a[1]), "r"(a[2]), "r"(a[3]), "r"(b[0]), "r"(b[1]));
}
__device__ __forceinline__ void ldsm_x4(uint32_t& r0, uint32_t& r1,
                                        uint32_t& r2, uint32_t& r3, uint32_t addr) {
    asm volatile("ldmatrix.sync.aligned.m8n8.x4.shared.b16 {%0,%1,%2,%3}, [%4];"
        : "=r"(r0), "=r"(r1), "=r"(r2), "=r"(r3) : "r"(addr));
}
__device__ __forceinline__ void ldsm_x4_trans(uint32_t& r0, uint32_t& r1,
                                              uint32_t& r2, uint32_t& r3, uint32_t addr) {
    asm volatile("ldmatrix.sync.aligned.m8n8.x4.trans.shared.b16 {%0,%1,%2,%3}, [%4];"
        : "=r"(r0), "=r"(r1), "=r"(r2), "=r"(r3) : "r"(addr));
}
__device__ __forceinline__ uint32_t packh(float x0, float x1) {
    __half2 h = __floats2half2_rn(x0, x1);
    return *(uint32_t*)&h;
}
__device__ __forceinline__ void cpasync16(void* s, const void* g) {
    uint32_t sa = (uint32_t)__cvta_generic_to_shared(s);
    asm volatile("cp.async.cg.shared.global [%0], [%1], 16;\n" :: "r"(sa), "l"(g));
}
#define CP_COMMIT() asm volatile("cp.async.commit_group;\n" ::: "memory")
#define CP_WAIT1()  asm volatile("cp.async.wait_group 1;\n"  ::: "memory")
#define CP_WAIT0()  asm volatile("cp.async.wait_group 0;\n"  ::: "memory")

// ---------------------------------------------------------------------------
// prep kernel: fp32 -> fp16
// ---------------------------------------------------------------------------
__global__ void cvt_f32h(const float4* __restrict__ src,
                         uint2* __restrict__ dst, int n4)
{
    int i = blockIdx.x * blockDim.x + threadIdx.x;
    if (i < n4) {
        float4 v = src[i];
        dst[i] = make_uint2(packh(v.x, v.y), packh(v.z, v.w));
    }
}

// ---------------------------------------------------------------------------
// single-pass fp16 GEMM:  C = A @ B^T.  A:[M,K] rm fp16, B:[N,K] rm fp16.
// Block 128x128, kTile 64 (fp16) -> 64 MMAs per barrier section, nk=16.
// 256 threads (8 warps, warp tile 32x64). 2-stage cp.async pipeline,
// fragments via ldmatrix.x4 (GST=36: 16B-aligned rows, conflict-free).
// MODE 0: fp32 store C.  MODE 1: QKV scatter epilogue (all coalesced u32;
// Q pre-scaled 0.125; V stored row-major like K — transposed at use by
// ldmatrix.trans in the attention kernel).
// ---------------------------------------------------------------------------
#define GST    36                          // smem row stride in u32 (32 data + 4 pad)
#define GCOMP  (128 * GST)                 // u32 per component per stage
#define GSTAGE (2 * GCOMP)                 // A, B
#define GEMM_SMEM (2 * GSTAGE * 4)         // 73728 bytes

template <int MODE>
__global__ void __launch_bounds__(256, 2)
gemm_h1(const __half* __restrict__ A, const __half* __restrict__ B,
        float* __restrict__ C, int K, int N)
{
    extern __shared__ uint32_t smu[];
    const uint32_t smb = (uint32_t)__cvta_generic_to_shared(smu);

    const int tid  = threadIdx.x;
    const int lane = tid & 31;
    const int w    = tid >> 5;
    const int gr   = lane >> 2;
    const int tig  = lane & 3;
    const int wm   = w & 3;              // 32-row quadrant
    const int wn   = w >> 2;             // 64-col half

    // ldmatrix lane mappings
    const int lrowA = (lane & 7) + ((lane >> 3) & 1) * 8;
    const int lcolA = (lane >> 4) * 4;
    const int lrowB = ((lane >> 4) & 1) * 8 + (lane & 7);
    const int lcolB = ((lane >> 3) & 1) * 4;

    const int row0 = blockIdx.y * 128;
    const int col0 = blockIdx.x * 128;

    float acc[2][8][4];
#pragma unroll
    for (int i = 0; i < 2; i++)
#pragma unroll
        for (int j = 0; j < 8; j++)
#pragma unroll
            for (int e = 0; e < 4; e++) acc[i][j][e] = 0.f;

    // stage loader: per component 128 rows x 64 fp16 (8 x 16B chunks per row)
    auto loadTile = [&](int s, int kt) {
        uint32_t* st = smu + (size_t)s * GSTAGE;
#pragma unroll
        for (int p = 0; p < 4; p++) {
            int c   = tid + 256 * p;         // 0..1023
            int row = c >> 3;
            int ch  = c & 7;
            uint32_t* d0 = st + row * GST + ch * 4;
            size_t ga = (size_t)(row0 + row) * K + kt + ch * 8;
            size_t gb = (size_t)(col0 + row) * K + kt + ch * 8;
            cpasync16(d0,         A + ga);
            cpasync16(d0 + GCOMP, B + gb);
        }
    };

    const int nk = K / 64;
    loadTile(0, 0);  CP_COMMIT();
    loadTile(1, 64); CP_COMMIT();

    for (int t = 0; t < nk; t++) {
        const int s = t & 1;
        if (t >= nk - 2) { CP_WAIT0(); } else { CP_WAIT1(); }
        __syncthreads();

        const uint32_t stb = smb + (uint32_t)s * GSTAGE * 4;

#pragma unroll
        for (int ks = 0; ks < 4; ks++) {
            const int base = ks * 8;
            uint32_t af[2][4];
#pragma unroll
            for (int mt = 0; mt < 2; mt++) {
                uint32_t aoff = ((wm * 32 + mt * 16 + lrowA) * GST + base + lcolA) * 4;
                ldsm_x4(af[mt][0], af[mt][1], af[mt][2], af[mt][3], stb + aoff);
            }
            uint32_t bf[8][2];
#pragma unroll
            for (int j = 0; j < 4; j++) {
                uint32_t boff = ((wn * 64 + j * 16 + lrowB) * GST + base + lcolB) * 4;
                ldsm_x4(bf[2 * j][0], bf[2 * j][1], bf[2 * j + 1][0], bf[2 * j + 1][1],
                        stb + GCOMP * 4 + boff);
            }
#pragma unroll
            for (int mt = 0; mt < 2; mt++)
#pragma unroll
                for (int nt = 0; nt < 8; nt++)
                    mma_f16(acc[mt][nt], af[mt], bf[nt]);
        }
        __syncthreads();
        if (t + 2 < nk) { loadTile(s, (t + 2) * 64); CP_COMMIT(); }
    }

    // ---- epilogue (MODE 1: all three sections coalesced u32 stores)
#pragma unroll
    for (int mt = 0; mt < 2; mt++) {
#pragma unroll
        for (int e2 = 0; e2 < 2; e2++) {
            int r = row0 + wm * 32 + mt * 16 + gr + e2 * 8;
#pragma unroll
            for (int nt = 0; nt < 8; nt++) {
                int n = col0 + wn * 64 + nt * 8 + 2 * tig;
                float v0 = acc[mt][nt][e2 * 2 + 0];
                float v1 = acc[mt][nt][e2 * 2 + 1];
                if (MODE == 0) {
                    *(float2*)&C[(size_t)r * N + n] = make_float2(v0, v1);
                } else {
                    int b   = r >> 11;            // / SEQ
                    int tk  = r & (SEQ - 1);
                    int sec = n >> 10;
                    int c   = n & 1023;
                    int h   = c >> 6;
                    int d   = c & 63;
                    int bh_ = b * NHEAD + h;
                    size_t i2 = (((size_t)bh_ * SEQ + tk) * HDIM + d) >> 1;
                    if (sec == 0) {
                        // Q: pre-scaled by 1/sqrt(D) (exact power of two)
                        ((uint32_t*)g_q)[i2] = packh(v0 * 0.125f, v1 * 0.125f);
                    } else if (sec == 1) {
                        ((uint32_t*)g_k)[i2] = packh(v0, v1);
                    } else {
                        ((uint32_t*)g_v)[i2] = packh(v0, v1);
                    }
                }
            }
        }
    }
}

// ---------------------------------------------------------------------------
// Causal flash attention, single-pass fp16 mma.sync. Br=128, Bc=64, D=64.
// 256 threads = 8 warps; warp w owns q rows [16w, 16w+16).
// Q fragments from gmem (pre-scaled at QKV epilogue). K via ldmatrix.x4,
// V (row-major [t][d]) via ldmatrix.x4.trans — transpose free at load.
// 3-stage cp.async ring, ONE __syncthreads per iter. P packed
// register-direct. Fully-masked warp-tiles skipped (bit-identical).
// LPT scheduling. grid: (SEQ/128, B*H)
// ---------------------------------------------------------------------------
#define AST 36                                   // smem row stride in u32
#define ATT_STG_U32 (2 * 64 * AST)               // Ks, Vs per stage
#define ATT_SMEM (3 * ATT_STG_U32 * 4)           // 55296 bytes

__global__ void __launch_bounds__(256, 2)
attn_h1()
{
    extern __shared__ uint32_t smu[];
    const uint32_t smb = (uint32_t)__cvta_generic_to_shared(smu);
    uint32_t* Stg = smu;                    // 3 stages of {Ks, Vs}

    const int tid  = threadIdx.x;
    const int lane = tid & 31;
    const int w    = tid >> 5;
    const int gr   = lane >> 2;
    const int tig  = lane & 3;
    const int m0   = w * 16;

    // ldmatrix lane mapping for K (non-trans B pairs)
    const int lrowB = ((lane >> 4) & 1) * 8 + (lane & 7);
    const int lcolB = ((lane >> 3) & 1) * 4;
    // ldmatrix.trans lane mapping for V ([t][d] tile -> B fragments)
    const int lrowV = ((lane >> 3) & 1) * 8 + (lane & 7);   // t within 16-row chunk
    const int lcolV = ((lane >> 4) & 1) * 4;                // +u32 col for n upper 8

    const int qb = gridDim.x - 1 - blockIdx.x;   // longest-processing-time first
    const int bh = blockIdx.y;
    const int b  = bh >> 4;
    const int h  = bh & 15;
    const int q0 = qb * 128;

    const size_t bhoff = (size_t)bh * SEQ * HDIM;

    // K/V prefetch (cp.async, 3-stage ring); V rows = t, same addressing as K
    auto loadKV = [&](int s, int kt) {
        const int k0 = kt * 64;
        uint32_t* st = Stg + s * ATT_STG_U32;
        for (int i = tid; i < 64 * 8; i += 256) {
            int row = i >> 3, ch = i & 7;
            uint32_t* d = st + row * AST + ch * 4;
            size_t g = bhoff + (size_t)(k0 + row) * HDIM + ch * 8;
            cpasync16(d,            g_k + g);
            cpasync16(d + 64 * AST, g_v + g);
        }
    };

    const int ktmax = 2 * qb + 1;          // >= 1 always
    loadKV(0, 0); CP_COMMIT();
    loadKV(1, 1); CP_COMMIT();

    // ---- Q fragments straight from gmem (already scaled by 0.125)
    uint32_t qf[4][4];
    {
        const uint32_t* qg = (const uint32_t*)(g_q + bhoff + (size_t)q0 * HDIM);
        const int r0i = (m0 + gr) * 32;          // u32 row stride = HDIM/2
        const int r1i = (m0 + gr + 8) * 32;
#pragma unroll
        for (int dk = 0; dk < 4; dk++) {
            qf[dk][0] = qg[r0i + dk * 8 + tig];
            qf[dk][1] = qg[r1i + dk * 8 + tig];
            qf[dk][2] = qg[r0i + dk * 8 + tig + 4];
            qf[dk][3] = qg[r1i + dk * 8 + tig + 4];
        }
    }

    float o[8][4];
#pragma unroll
    for (int nt = 0; nt < 8; nt++)
#pragma unroll
        for (int e = 0; e < 4; e++) o[nt][e] = 0.f;
    float mrow[2] = {-1e30f, -1e30f};
    float lrow[2] = {0.f, 0.f};

    for (int kt = 0; kt <= ktmax; kt++) {
        const int s = kt % 3;
        if (kt < ktmax) { CP_WAIT1(); } else { CP_WAIT0(); }
        __syncthreads();                       // single barrier per iter
        if (kt + 2 <= ktmax) { loadKV((kt + 2) % 3, kt + 2); CP_COMMIT(); }

        const int k0 = kt * 64;
        // fully-masked warp-tile: all columns beyond this warp's rows.
        // exp(-1e30)=0 makes skipping bit-identical; only occurs at kt=ktmax
        // so the loadKV above is never skipped.
        if (k0 > q0 + m0 + 15) continue;

        const uint32_t ksb = smb + (uint32_t)s * ATT_STG_U32 * 4;
        const uint32_t vtb = ksb + 64 * AST * 4;

        // ---- S = Q K^T (single pass), K fragments via ldmatrix
        float sfr[8][4];
#pragma unroll
        for (int nt = 0; nt < 8; nt++)
#pragma unroll
            for (int e = 0; e < 4; e++) sfr[nt][e] = 0.f;

#pragma unroll
        for (int dk = 0; dk < 4; dk++) {
            uint32_t kf[8][2];
#pragma unroll
            for (int j = 0; j < 4; j++) {
                uint32_t koff = ((j * 16 + lrowB) * AST + dk * 8 + lcolB) * 4;
                ldsm_x4(kf[2 * j][0], kf[2 * j][1], kf[2 * j + 1][0], kf[2 * j + 1][1],
                        ksb + koff);
            }
#pragma unroll
            for (int nt = 0; nt < 8; nt++)
                mma_f16(sfr[nt], qf[dk], kf[nt]);
        }

        // ---- causal mask (only near the diagonal)
        if (k0 + 63 > q0 + m0) {
#pragma unroll
            for (int nt = 0; nt < 8; nt++)
#pragma unroll
                for (int e = 0; e < 4; e++) {
                    int rg = q0 + m0 + gr + (e >> 1) * 8;
                    int cg = k0 + nt * 8 + 2 * tig + (e & 1);
                    if (cg > rg) sfr[nt][e] = -1e30f;
                }
        }

        // ---- online softmax (thread rows: gr, gr+8); p kept in sfr
        float mx0 = -1e30f, mx1 = -1e30f;
#pragma unroll
        for (int nt = 0; nt < 8; nt++) {
            mx0 = fmaxf(mx0, fmaxf(sfr[nt][0], sfr[nt][1]));
            mx1 = fmaxf(mx1, fmaxf(sfr[nt][2], sfr[nt][3]));
        }
        mx0 = fmaxf(mx0, __shfl_xor_sync(0xffffffffu, mx0, 1));
        mx0 = fmaxf(mx0, __shfl_xor_sync(0xffffffffu, mx0, 2));
        mx1 = fmaxf(mx1, __shfl_xor_sync(0xffffffffu, mx1, 1));
        mx1 = fmaxf(mx1, __shfl_xor_sync(0xffffffffu, mx1, 2));

        float nm0 = fmaxf(mrow[0], mx0);
        float nm1 = fmaxf(mrow[1], mx1);
        float f0  = __expf(mrow[0] - nm0);
        float f1  = __expf(mrow[1] - nm1);

        float ps0 = 0.f, ps1 = 0.f;
#pragma unroll
        for (int nt = 0; nt < 8; nt++) {
            sfr[nt][0] = __expf(sfr[nt][0] - nm0);
            sfr[nt][1] = __expf(sfr[nt][1] - nm0);
            sfr[nt][2] = __expf(sfr[nt][2] - nm1);
            sfr[nt][3] = __expf(sfr[nt][3] - nm1);
            ps0 += sfr[nt][0] + sfr[nt][1];
            ps1 += sfr[nt][2] + sfr[nt][3];
        }
        ps0 += __shfl_xor_sync(0xffffffffu, ps0, 1);
        ps0 += __shfl_xor_sync(0xffffffffu, ps0, 2);
        ps1 += __shfl_xor_sync(0xffffffffu, ps1, 1);
        ps1 += __shfl_xor_sync(0xffffffffu, ps1, 2);

        lrow[0] = lrow[0] * f0 + ps0;
        lrow[1] = lrow[1] * f1 + ps1;
        mrow[0] = nm0;
        mrow[1] = nm1;
#pragma unroll
        for (int nt = 0; nt < 8; nt++) {
            o[nt][0] *= f0; o[nt][1] *= f0;
            o[nt][2] *= f1; o[nt][3] *= f1;
        }

        // ---- O += P V (single pass), P register-direct, V via ldmatrix.trans
        // V tile rows = t (k dim), cols = d (n dim); .trans yields B fragments.
#pragma unroll
        for (int kk = 0; kk < 4; kk++) {
            uint32_t pf[4];
            pf[0] = packh(sfr[2 * kk    ][0], sfr[2 * kk    ][1]);
            pf[1] = packh(sfr[2 * kk    ][2], sfr[2 * kk    ][3]);
            pf[2] = packh(sfr[2 * kk + 1][0], sfr[2 * kk + 1][1]);
            pf[3] = packh(sfr[2 * kk + 1][2], sfr[2 * kk + 1][3]);
            uint32_t vf[8][2];
#pragma unroll
            for (int j = 0; j < 4; j++) {
                uint32_t voff = ((kk * 16 + lrowV) * AST + j * 8 + lcolV) * 4;
                ldsm_x4_trans(vf[2 * j][0], vf[2 * j][1],
                              vf[2 * j + 1][0], vf[2 * j + 1][1],
                              vtb + voff);
            }
#pragma unroll
            for (int nt = 0; nt < 8; nt++)
                mma_f16(o[nt], pf, vf[nt]);
        }
    }

    // ---- normalize and store to g_ao (single fp16, [B*T, C])
    float inv0 = 1.0f / lrow[0];
    float inv1 = 1.0f / lrow[1];
    int r0 = q0 + m0 + gr;
    uint32_t* ao = (uint32_t*)g_ao;
#pragma unroll
    for (int nt = 0; nt < 8; nt++) {
        size_t cu = (size_t)h * 32 + nt * 4 + tig;   // u32 col
        ao[(size_t)(b * SEQ + r0) * (EMBED / 2) + cu] =
            packh(o[nt][0] * inv0, o[nt][1] * inv0);
        ao[(size_t)(b * SEQ + r0 + 8) * (EMBED / 2) + cu] =
            packh(o[nt][2] * inv1, o[nt][3] * inv1);
    }
}

// ---------------------------------------------------------------------------
extern "C" void kernel_launch(void* const* d_in, const int* in_sizes, int n_in,
                              void* d_out, int out_size)
{
    const float* x      = (const float*)d_in[0];   // [4,2048,1024]
    const float* W_qkv  = (const float*)d_in[1];   // [3072,1024]
    const float* W_proj = (const float*)d_in[2];   // [1024,1024]
    float* out = (float*)d_out;                    // [4,2048,1024]

    __half *xp, *wq, *wp, *ao;
    cudaGetSymbolAddress((void**)&xp, g_x);
    cudaGetSymbolAddress((void**)&wq, g_wq);
    cudaGetSymbolAddress((void**)&wp, g_wp);
    cudaGetSymbolAddress((void**)&ao, g_ao);

    // 0) prep: everything to single fp16
    {
        int n1 = MROWS * EMBED / 4, n2 = 3 * EMBED * EMBED / 4, n3 = EMBED * EMBED / 4;
        cvt_f32h<<<(n1 + 255) / 256, 256>>>((const float4*)x, (uint2*)xp, n1);
        cvt_f32h<<<(n2 + 255) / 256, 256>>>((const float4*)W_qkv, (uint2*)wq, n2);
        cvt_f32h<<<(n3 + 255) / 256, 256>>>((const float4*)W_proj, (uint2*)wp, n3);
    }

    // 1) QKV projection (single-pass fp16, kTile=64) with scatter epilogue
    {
        cudaFuncSetAttribute((const void*)gemm_h1<1>,
                             cudaFuncAttributeMaxDynamicSharedMemorySize, GEMM_SMEM);
        dim3 grid(3 * EMBED / 128, MROWS / 128);
        gemm_h1<1><<<grid, 256, GEMM_SMEM>>>(xp, wq, nullptr, EMBED, 3 * EMBED);
    }

    // 2) causal flash attention -> g_ao (single fp16)
    {
        cudaFuncSetAttribute((const void*)attn_h1,
                             cudaFuncAttributeMaxDynamicSharedMemorySize, ATT_SMEM);
        dim3 grid(SEQ / 128, BATCH * NHEAD);
        attn_h1<<<grid, 256, ATT_SMEM>>>();
    }

    // 3) output projection (single-pass fp16, kTile=64) -> d_out (fp32)
    {
        cudaFuncSetAttribute((const void*)gemm_h1<0>,
                             cudaFuncAttributeMaxDynamicSharedMemorySize, GEMM_SMEM);
        dim3 grid(EMBED / 128, MROWS / 128);
        gemm_h1<0><<<grid, 256, GEMM_SMEM>>>(ao, wp, out, EMBED, EMBED);
    }
}